// round 14
// baseline (speedup 1.0000x reference)
#include <cuda_runtime.h>
#include <cuda_bf16.h>
#include <math.h>
#include <stdint.h>

#define EPSV  1e-5f
#define SLOPE 0.01f

#define B_    16
#define C_    512
#define NHW   4096
#define D_    128
#define K_    16
#define TN    64
#define TILES 64   // NHW / TN
#define NTILE (B_ * TILES)

// ---------------- PTX helpers ----------------
__device__ __forceinline__ uint32_t smem_to_u32(const void* p) {
  uint32_t a;
  asm("{ .reg .u64 t; cvta.to.shared.u64 t, %1; cvt.u32.u64 %0, t; }" : "=r"(a) : "l"(p));
  return a;
}
__device__ __forceinline__ void ldsm4(uint32_t* r, uint32_t addr) {
  asm volatile("ldmatrix.sync.aligned.m8n8.x4.shared.b16 {%0,%1,%2,%3}, [%4];"
               : "=r"(r[0]), "=r"(r[1]), "=r"(r[2]), "=r"(r[3]) : "r"(addr));
}
__device__ __forceinline__ void mma_bf16(float* d, const uint32_t* a,
                                         uint32_t b0, uint32_t b1) {
  asm volatile(
      "mma.sync.aligned.m16n8k16.row.col.f32.bf16.bf16.f32 "
      "{%0,%1,%2,%3}, {%4,%5,%6,%7}, {%8,%9}, {%0,%1,%2,%3};"
      : "+f"(d[0]), "+f"(d[1]), "+f"(d[2]), "+f"(d[3])
      : "r"(a[0]), "r"(a[1]), "r"(a[2]), "r"(a[3]), "r"(b0), "r"(b1));
}
__device__ __forceinline__ void cpasync16(uint32_t dst, const void* src) {
  asm volatile("cp.async.cg.shared.global [%0], [%1], 16;" :: "r"(dst), "l"(src));
}
__device__ __forceinline__ uint32_t cvt_bf16x2(float hi_elem, float lo_elem) {
  uint32_t r;
  asm("cvt.rn.bf16x2.f32 %0, %1, %2;" : "=r"(r) : "f"(hi_elem), "f"(lo_elem));
  return r;
}
__device__ __forceinline__ unsigned long long ffma2(unsigned long long a,
                                                    unsigned long long b,
                                                    unsigned long long c) {
  unsigned long long d;
  asm("fma.rn.f32x2 %0, %1, %2, %3;" : "=l"(d) : "l"(a), "l"(b), "l"(c));
  return d;
}
__device__ __forceinline__ unsigned long long pack2(float lo, float hi) {
  unsigned long long r;
  asm("mov.b64 %0, {%1, %2};" : "=l"(r) : "f"(lo), "f"(hi));
  return r;
}
__device__ __forceinline__ void unpack2(unsigned long long v, float& lo, float& hi) {
  asm("mov.b64 {%0, %1}, %2;" : "=f"(lo), "=f"(hi) : "l"(v));
}
#define CP_COMMIT() asm volatile("cp.async.commit_group;" ::: "memory")
#define CP_WAIT1()  asm volatile("cp.async.wait_group 1;" ::: "memory")
#define SWZ(x) ((x) ^ (((x) >> 3) & 0x70))

// ---------------- scratch (device globals) ----------------
__device__ __align__(16) float4 g_abn4[C_];   // (sp, tp, g1, h1)
__device__ float g_s2[D_], g_t2[D_];
__device__ float g_c2k[K_];
__device__ __align__(16) __nv_bfloat16 g_wbf_hi[D_ * C_];  // (D,C) K-major
__device__ __align__(16) __nv_bfloat16 g_wbf_lo[D_ * C_];
__device__ float g_spa[B_ * NHW];
__device__ float g_chn[B_ * C_];
__device__ float g_partE[NTILE * K_ * D_];   // 8 MB
__device__ float g_partAsum[NTILE * K_];
__device__ float g_encU[B_ * K_ * D_];
__device__ float g_sqp[B_ * 8];
__device__ int   g_ctr;

// ---------------- fold ABN constants (+ work-counter reset) ----------------
__global__ void k_prep_c(const float* __restrict__ pg, const float* __restrict__ pb,
                         const float* __restrict__ pm, const float* __restrict__ pv,
                         const float* __restrict__ a1g, const float* __restrict__ a1b,
                         const float* __restrict__ a1m, const float* __restrict__ a1v) {
  if (blockIdx.x == 0 && threadIdx.x == 0) g_ctr = 0;
  const int c = blockIdx.x * 256 + threadIdx.x;
  if (c < C_) {
    float s = pg[c] * rsqrtf(pv[c] + EPSV);
    float s1 = a1g[c] * rsqrtf(a1v[c] + EPSV);
    g_abn4[c] = make_float4(s, pb[c] - pm[c] * s, s1, a1b[c] - a1m[c] * s1);
  }
}
__global__ void k_prep_d(const float* __restrict__ cb, const float* __restrict__ a2g,
                         const float* __restrict__ a2b, const float* __restrict__ a2m,
                         const float* __restrict__ a2v, const float* __restrict__ cw) {
  const int t = threadIdx.x;
  if (t < D_) {
    float s2 = a2g[t] * rsqrtf(a2v[t] + EPSV);
    g_s2[t] = s2;
    g_t2[t] = cb[t] * s2 + a2b[t] - a2m[t] * s2;
  }
  if (t < K_) {
    float a = 0.f;
    for (int d = 0; d < D_; d++) { float v = cw[t * D_ + d]; a += v * v; }
    g_c2k[t] = a;
  }
}

// ---------------- split conv_w into bf16 hi/lo ----------------
__global__ void k_wsplit(const float* __restrict__ w) {
  const int i = blockIdx.x * 256 + threadIdx.x;
  if (i < D_ * C_) {
    float v = w[i];
    __nv_bfloat16 hi = __float2bfloat16(v);
    g_wbf_hi[i] = hi;
    g_wbf_lo[i] = __float2bfloat16(v - __bfloat162float(hi));
  }
}

// ---------------- fused main kernel (TN=64 tiles for load balance) ----------------
// phase 1 (bytes): A_hi0 @0 (8K), A_lo0 @8K, A_hi1 @16K, A_lo1 @24K (32K total),
//                  B_hi0 @32K, B_lo0 @48K, B_hi1 @64K, B_lo1 @80K (96K end)
// phase 2 (floats from 0): X 64x132=8448, A @8448 (1024), cw @9472 (2048),
//                  r2 @11520 (7x1088=7616), sc @19136, c2 @19152
//                  EP alias @11520 (4096), asp @15616 (128)
// coef cache @98304: abn4 8KB + spa_w 2KB
#define SM_A_HI(s) ((s) * 16384)
#define SM_A_LO(s) ((s) * 16384 + 8192)
#define SM_B_HI(s) (32768 + (s) * 32768)
#define SM_B_LO(s) (32768 + (s) * 32768 + 16384)
#define SM_COEF    98304
#define SMEM_BYTES 108544
#define NCHUNK 8   // C_ / 64
#define NT 512
#define GRID_PERSIST 148

__global__ __launch_bounds__(NT)
void k_main(const float* __restrict__ x, const float* __restrict__ spa_w,
            const float* __restrict__ codewords, const float* __restrict__ scalek) {
  extern __shared__ char smem[];
  __shared__ int s_wk;
  float* smf = reinterpret_cast<float*>(smem);
  const uint32_t smem_base = smem_to_u32(smem);
  const int t = threadIdx.x;
  const int wid = t >> 5, lane = t & 31;
  const int warp_m = wid & 3;      // 4 warps over M=64 (16 rows each)
  const int warp_n = wid >> 2;     // 4 warps over N=128 (32 cols each)
  const int n = t & 63;            // spatial row this thread transforms
  const int cg = t >> 6;           // channel eighth (0..7): 8 channels each
  const int w_d = t >> 2, w_q = t & 3;

  // persistent coefficient cache
  float4* s_ab = reinterpret_cast<float4*>(smem + SM_COEF);
  float*  s_sw = reinterpret_cast<float*>(smem + SM_COEF + 8192);
  s_ab[t] = g_abn4[t];
  s_sw[t] = spa_w[t];
  __syncthreads();

  while (true) {
    if (t == 0) s_wk = atomicAdd(&g_ctr, 1);
    __syncthreads();
    const int wk = s_wk;
    if (wk >= NTILE) break;
    const int b = wk >> 6;
    const int tile = wk & 63;
    const int n0 = tile * TN;
    const float* xb = x + ((size_t)b * C_) * NHW + n0;

    float acc[4][4];
#pragma unroll
    for (int j = 0; j < 4; j++)
#pragma unroll
      for (int q = 0; q < 4; q++) acc[j][q] = 0.f;
    float spa_acc = 0.f;
    float xcur[8];

    auto issue_w = [&](int cc, int s) {
      const __nv_bfloat16* gh = &g_wbf_hi[w_d * C_ + cc * 64 + w_q * 16];
      const __nv_bfloat16* gl = &g_wbf_lo[w_d * C_ + cc * 64 + w_q * 16];
      const uint32_t bh = smem_base + SM_B_HI(s);
      const uint32_t bl = smem_base + SM_B_LO(s);
#pragma unroll
      for (int j = 0; j < 2; j++) {
        const uint32_t bo = SWZ((uint32_t)(w_d * 128 + w_q * 32 + j * 16));
        cpasync16(bh + bo, gh + j * 8);
        cpasync16(bl + bo, gl + j * 8);
      }
    };
    auto fetch_x = [&](int cc) {
      const float* gx = xb + (size_t)(cc * 64 + cg * 8) * NHW + n;
#pragma unroll
      for (int j = 0; j < 8; j++) xcur[j] = gx[(size_t)j * NHW];
    };

    issue_w(0, 0);
    CP_COMMIT();
    fetch_x(0);

    for (int cc = 0; cc < NCHUNK; cc++) {
      const int s = cc & 1;

      // ---- transform xcur -> A[s] hi/lo tiles (8 channels/thread) ----
      const int c0 = cc * 64 + cg * 8;
      {
        uint32_t hp[4], lp[4];
#pragma unroll
        for (int jp = 0; jp < 4; jp++) {
          float yv[2];
#pragma unroll
          for (int u = 0; u < 2; u++) {
            const int jj = jp * 2 + u;
            const int c = c0 + jj;
            const float4 cf = s_ab[c];
            float xn = fmaf(xcur[jj], cf.x, cf.y);
            xn = (xn >= 0.f) ? xn : SLOPE * xn;
            spa_acc = fmaf(xn, s_sw[c], spa_acc);
            float y = fmaf(xn, cf.z, cf.w);
            yv[u] = (y >= 0.f) ? y : SLOPE * y;
          }
          const uint32_t b0 = __float_as_uint(yv[0]);
          const uint32_t b1 = __float_as_uint(yv[1]);
          hp[jp] = __byte_perm(b0, b1, 0x7632);
          const float lo0 = yv[0] - __uint_as_float(b0 & 0xFFFF0000u);
          const float lo1 = yv[1] - __uint_as_float(b1 & 0xFFFF0000u);
          lp[jp] = cvt_bf16x2(lo1, lo0);
        }
        const uint32_t bo = SWZ((uint32_t)(n * 128 + cg * 16));
        *reinterpret_cast<uint4*>(smem + SM_A_HI(s) + bo) = make_uint4(hp[0], hp[1], hp[2], hp[3]);
        *reinterpret_cast<uint4*>(smem + SM_A_LO(s) + bo) = make_uint4(lp[0], lp[1], lp[2], lp[3]);
      }

      __syncthreads();     // A[s] ready; all mma(cc-1) done

      if (cc + 1 < NCHUNK) issue_w(cc + 1, s ^ 1);
      CP_COMMIT();
      CP_WAIT1();          // B[s] resident

      if (cc + 1 < NCHUNK) fetch_x(cc + 1);

      // ---- tensor-core GEMM (4M x 4N warps, 16x32 each), pass-major ----
#pragma unroll
      for (int ks = 0; ks < 4; ks++) {
        uint32_t aH[4], aL[4];
        {
          const uint32_t row = warp_m * 16 + (lane & 15);
          const uint32_t colb = ks * 32 + ((lane >> 4) << 4);
          const uint32_t sw = SWZ(row * 128 + colb);
          ldsm4(aH, smem_base + SM_A_HI(s) + sw);
          ldsm4(aL, smem_base + SM_A_LO(s) + sw);
        }
        uint32_t bh[2][4], bl[2][4];
#pragma unroll
        for (int p = 0; p < 2; p++) {
          const uint32_t d = warp_n * 32 + p * 16 + (lane & 7) + ((lane >> 4) & 1) * 8;
          const uint32_t colb = ks * 32 + (((lane >> 3) & 1) << 4);
          const uint32_t sw = SWZ(d * 128 + colb);
          ldsm4(bh[p], smem_base + SM_B_HI(s) + sw);
          ldsm4(bl[p], smem_base + SM_B_LO(s) + sw);
        }
        // pass 1: hi*hi (4 independent accumulators)
        mma_bf16(acc[0], aH, bh[0][0], bh[0][1]);
        mma_bf16(acc[1], aH, bh[0][2], bh[0][3]);
        mma_bf16(acc[2], aH, bh[1][0], bh[1][1]);
        mma_bf16(acc[3], aH, bh[1][2], bh[1][3]);
        // pass 2: hi*lo
        mma_bf16(acc[0], aH, bl[0][0], bl[0][1]);
        mma_bf16(acc[1], aH, bl[0][2], bl[0][3]);
        mma_bf16(acc[2], aH, bl[1][0], bl[1][1]);
        mma_bf16(acc[3], aH, bl[1][2], bl[1][3]);
        // pass 3: lo*hi
        mma_bf16(acc[0], aL, bh[0][0], bh[0][1]);
        mma_bf16(acc[1], aL, bh[0][2], bh[0][3]);
        mma_bf16(acc[2], aL, bh[1][0], bh[1][1]);
        mma_bf16(acc[3], aL, bh[1][2], bh[1][3]);
      }
      // no trailing barrier: next transform writes A[s^1] (disjoint)
    }

    // ---- spatial SE combine (8 partials per n) + sigmoid ----
    smf[t] = spa_acc;
    __syncthreads();   // also fences the final mma before phase-2 smem reuse
    if (t < TN) {
      float sps = 0.f;
#pragma unroll
      for (int j = 0; j < 8; j++) sps += smf[t + j * 64];
      g_spa[b * NHW + n0 + t] = 1.f / (1.f + __expf(-sps));
    }
    __syncthreads();

    // ---- phase 2 smem layout (floats) ----
    float* s_X  = smf;            // 64 x 132
    float* s_A  = smf + 8448;     // 64 x 16
    float* s_cw = smf + 9472;     // 16 x 128
    float* s_r2 = smf + 11520;    // 7 x 1088
    float* s_sc = smf + 19136;    // 16
    float* s_c2 = smf + 19152;    // 16

    // ---- epilogue: acc -> abn2 + leaky -> s_X ----
    {
      const int quad = lane >> 2, qp = lane & 3;
      const int r0 = warp_m * 16 + quad;
#pragma unroll
      for (int nt = 0; nt < 4; nt++) {
        const int cd = warp_n * 32 + nt * 8 + qp * 2;
        const float s2a = g_s2[cd], s2b = g_s2[cd + 1];
        const float t2a = g_t2[cd], t2b = g_t2[cd + 1];
        float z0 = fmaf(acc[nt][0], s2a, t2a); z0 = (z0 >= 0.f) ? z0 : SLOPE * z0;
        float z1 = fmaf(acc[nt][1], s2b, t2b); z1 = (z1 >= 0.f) ? z1 : SLOPE * z1;
        float z2 = fmaf(acc[nt][2], s2a, t2a); z2 = (z2 >= 0.f) ? z2 : SLOPE * z2;
        float z3 = fmaf(acc[nt][3], s2b, t2b); z3 = (z3 >= 0.f) ? z3 : SLOPE * z3;
        *reinterpret_cast<float2*>(&s_X[r0 * 132 + cd])       = make_float2(z0, z1);
        *reinterpret_cast<float2*>(&s_X[(r0 + 8) * 132 + cd]) = make_float2(z2, z3);
      }
    }
#pragma unroll
    for (int i = 0; i < 4; i++) s_cw[t * 4 + i] = codewords[t * 4 + i];
    if (t < K_) { s_sc[t] = scalek[t]; s_c2[t] = g_c2k[t]; }
    __syncthreads();

    // ---- scaled-L2 softmax assignment A (8 threads per position, 16 dims each) ----
    {
      const int nn = t & 63;
      const int q = t >> 6;            // 0..7
      const float* xr = &s_X[nn * 132 + q * 16];
      unsigned long long px2p = 0ull;
      unsigned long long pxcp[16];
#pragma unroll
      for (int k = 0; k < 16; k++) pxcp[k] = 0ull;
#pragma unroll
      for (int ch = 0; ch < 4; ch++) {
        const ulonglong2 xp = *reinterpret_cast<const ulonglong2*>(xr + ch * 4);
        px2p = ffma2(xp.x, xp.x, px2p);
        px2p = ffma2(xp.y, xp.y, px2p);
        const int dd = q * 16 + ch * 4;
#pragma unroll
        for (int k = 0; k < 16; k++) {
          const ulonglong2 cp = *reinterpret_cast<const ulonglong2*>(&s_cw[k * 128 + dd]);
          pxcp[k] = ffma2(xp.x, cp.x, pxcp[k]);
          pxcp[k] = ffma2(xp.y, cp.y, pxcp[k]);
        }
      }
      float px2, pxc[16];
      {
        float lo, hi;
        unpack2(px2p, lo, hi);
        px2 = lo + hi;
#pragma unroll
        for (int k = 0; k < 16; k++) { unpack2(pxcp[k], lo, hi); pxc[k] = lo + hi; }
      }
      if (q) {
        float* sr = s_r2 + (q - 1) * 1088;
        sr[nn] = px2;
#pragma unroll
        for (int k = 0; k < 16; k++) sr[64 + k * 64 + nn] = pxc[k];
      }
      __syncthreads();
      if (!q) {
        float x2 = px2;
#pragma unroll
        for (int j = 0; j < 7; j++) x2 += s_r2[j * 1088 + nn];
        float sl[16];
        float m = -1e30f;
#pragma unroll
        for (int k = 0; k < 16; k++) {
          float xc = pxc[k];
#pragma unroll
          for (int j = 0; j < 7; j++) xc += s_r2[j * 1088 + 64 + k * 64 + nn];
          float v = s_sc[k] * (x2 - 2.f * xc + s_c2[k]);
          sl[k] = v;
          m = fmaxf(m, v);
        }
        float ssum = 0.f;
#pragma unroll
        for (int k = 0; k < 16; k++) { float e2 = __expf(sl[k] - m); sl[k] = e2; ssum += e2; }
        const float inv = 1.f / ssum;
#pragma unroll
        for (int k = 0; k < 16; k++) s_A[nn * 16 + k] = sl[k] * inv;
      }
      __syncthreads();
    }

    // ---- partial E = A^T @ X (broadcast form, f32x2; thread = (d, n-group)) ----
    {
      const int d = t & 127;
      const int ng = t >> 7;           // 0..3, 16 n's each
      unsigned long long e2[8];
#pragma unroll
      for (int j = 0; j < 8; j++) e2[j] = 0ull;
      const int nb0 = ng * 16;
      for (int nn = nb0; nn < nb0 + 16; nn++) {
        const float xv = s_X[nn * 132 + d];
        const unsigned long long xvp = pack2(xv, xv);
        const ulonglong2* ar = reinterpret_cast<const ulonglong2*>(&s_A[nn * 16]);
#pragma unroll
        for (int j2 = 0; j2 < 4; j2++) {
          const ulonglong2 ap = ar[j2];
          e2[j2 * 2]     = ffma2(ap.x, xvp, e2[j2 * 2]);
          e2[j2 * 2 + 1] = ffma2(ap.y, xvp, e2[j2 * 2 + 1]);
        }
      }
      float e[16];
#pragma unroll
      for (int j = 0; j < 8; j++) unpack2(e2[j], e[2 * j], e[2 * j + 1]);
      float* s_EP  = smf + 11520;     // alias s_r2 (softmax done)
      float* s_asp = smf + 15616;     // 128 floats
      if (ng >= 2) {
#pragma unroll
        for (int k = 0; k < 16; k++) s_EP[(ng - 2) * 2048 + k * 128 + d] = e[k];
      }
      if (t < 128) {                   // ng == 0: also compute asum partials
        const int kk = t >> 3, seg = t & 7;
        float a = 0.f;
        for (int nn = seg * 8; nn < seg * 8 + 8; nn++) a += s_A[nn * 16 + kk];
        s_asp[t] = a;
      }
      __syncthreads();
      if (ng < 2) {
#pragma unroll
        for (int k = 0; k < 16; k++) e[k] += s_EP[ng * 2048 + k * 128 + d];
      }
      if (t < 16) {
        float a = 0.f;
#pragma unroll
        for (int j = 0; j < 8; j++) a += s_asp[t * 8 + j];
        g_partAsum[wk * K_ + t] = a;
      }
      __syncthreads();
      if (ng == 1) {
#pragma unroll
        for (int k = 0; k < 16; k++) s_EP[k * 128 + d] = e[k];
      }
      __syncthreads();
      if (ng == 0) {
#pragma unroll
        for (int k = 0; k < 16; k++) {
          e[k] += s_EP[k * 128 + d];
          g_partE[(wk * K_ + k) * D_ + d] = e[k];
        }
      }
    }
    __syncthreads();   // protect smem before next tile
  }
}

// ---------------- stage 1 reduce: grid 128 = b x 8 slices ----------------
__global__ void k_red1(const float* __restrict__ codewords) {
  __shared__ float s_as2[2];
  __shared__ float s_red[256];
  const int blk = blockIdx.x;
  const int b = blk >> 3, slice = blk & 7;
  const int t = threadIdx.x;
  const int idx = slice * 256 + t;        // 0..2047 within this b
  if (t < 2) {
    const int k = slice * 2 + t;
    float a = 0.f;
    for (int tile = 0; tile < TILES; tile++)
      a += g_partAsum[(b * TILES + tile) * K_ + k];
    s_as2[t] = a;
  }
  __syncthreads();
  float e = 0.f;
  const int base = b * TILES * 2048 + idx;
  for (int tile = 0; tile < TILES; tile++) e += g_partE[base + tile * 2048];
  e -= s_as2[t >> 7] * codewords[idx];    // idx == k*128 + d in (K,D) layout
  g_encU[b * 2048 + idx] = e;
  s_red[t] = e * e;
  __syncthreads();
  for (int s = 128; s > 0; s >>= 1) {
    if (t < s) s_red[t] += s_red[t + s];
    __syncthreads();
  }
  if (t == 0) g_sqp[blk] = s_red[0];
}

// ---------------- write normalized enc to d_out ----------------
__global__ void k_encw(float* __restrict__ out_enc) {
  const int idx = blockIdx.x * 256 + threadIdx.x;  // 32768 total
  const int b = idx >> 11;
  float s = 0.f;
#pragma unroll
  for (int j = 0; j < 8; j++) s += g_sqp[b * 8 + j];
  const float rn = 1.f / fmaxf(sqrtf(s), 1e-12f);
  out_enc[idx] = g_encU[idx] * rn;
}

// ---------------- channel SE (norm folded in post-dot) ----------------
__global__ __launch_bounds__(256)
void k_chse(const float* __restrict__ se_w, const float* __restrict__ se_b) {
  __shared__ float sw[2048];
  __shared__ float s_rn[16];
  const int c = blockIdx.x;
  const int t = threadIdx.x;
  if (t < 16) {
    float s = 0.f;
#pragma unroll
    for (int j = 0; j < 8; j++) s += g_sqp[t * 8 + j];
    s_rn[t] = 1.f / fmaxf(sqrtf(s), 1e-12f);
  }
  const float* wr = se_w + (size_t)c * 2048;
#pragma unroll
  for (int i = 0; i < 8; i++) sw[t + i * 256] = wr[t + i * 256];
  __syncthreads();
  const int w = t >> 5, lane = t & 31;
  const float bias = se_b[c];
#pragma unroll
  for (int bb = 0; bb < 2; bb++) {
    const int b = w * 2 + bb;
    const float* er = g_encU + b * 2048;
    float p = 0.f;
#pragma unroll 8
    for (int i = 0; i < 64; i++) {
      const int idx = lane + (i << 5);
      p = fmaf(er[idx], sw[idx], p);
    }
#pragma unroll
    for (int o = 16; o > 0; o >>= 1) p += __shfl_xor_sync(0xffffffffu, p, o);
    if (lane == 0)
      g_chn[b * C_ + c] = 1.f / (1.f + __expf(-fmaf(p, s_rn[b], bias)));
  }
}

// ---------------- final gating: out = x * spa_se * chn_se ----------------
__global__ void k_out(const float* __restrict__ x, float* __restrict__ out) {
  const int i = blockIdx.x * 256 + threadIdx.x;
  float4 v = reinterpret_cast<const float4*>(x)[i];
  const int b = i >> 19;
  const int rem = i & 524287;
  const int c = rem >> 10;
  const int n4 = rem & 1023;
  const float4 sp = reinterpret_cast<const float4*>(g_spa)[b * 1024 + n4];
  const float ch = g_chn[b * C_ + c];
  float4 o;
  o.x = v.x * sp.x * ch;
  o.y = v.y * sp.y * ch;
  o.z = v.z * sp.z * ch;
  o.w = v.w * sp.w * ch;
  reinterpret_cast<float4*>(out)[i] = o;
}

extern "C" void kernel_launch(void* const* d_in, const int* in_sizes, int n_in,
                              void* d_out, int out_size) {
  const float* x    = (const float*)d_in[0];
  const float* pg   = (const float*)d_in[1];
  const float* pb   = (const float*)d_in[2];
  const float* pm   = (const float*)d_in[3];
  const float* pv   = (const float*)d_in[4];
  const float* a1g  = (const float*)d_in[5];
  const float* a1b  = (const float*)d_in[6];
  const float* a1m  = (const float*)d_in[7];
  const float* a1v  = (const float*)d_in[8];
  const float* cwv  = (const float*)d_in[9];   // conv_w (D, C)
  const float* cb   = (const float*)d_in[10];
  const float* a2g  = (const float*)d_in[11];
  const float* a2b  = (const float*)d_in[12];
  const float* a2m  = (const float*)d_in[13];
  const float* a2v  = (const float*)d_in[14];
  const float* cdw  = (const float*)d_in[15];  // codewords (K, D)
  const float* sck  = (const float*)d_in[16];  // scale (K,)
  const float* sew  = (const float*)d_in[17];  // se_w (C, K*D)
  const float* seb  = (const float*)d_in[18];
  const float* spw  = (const float*)d_in[19];  // spa_w (C,)
  float* out = (float*)d_out;

  cudaFuncSetAttribute(k_main, cudaFuncAttributeMaxDynamicSharedMemorySize, SMEM_BYTES);

  k_prep_c<<<2, 256>>>(pg, pb, pm, pv, a1g, a1b, a1m, a1v);
  k_prep_d<<<1, 128>>>(cb, a2g, a2b, a2m, a2v, cdw);
  k_wsplit<<<(D_ * C_ + 255) / 256, 256>>>(cwv);
  k_main<<<GRID_PERSIST, NT, SMEM_BYTES>>>(x, spw, cdw, sck);
  k_red1<<<128, 256>>>(cdw);
  k_encw<<<128, 256>>>(out);
  k_chse<<<C_, 256>>>(sew, seb);
  k_out<<<(B_ * C_ * NHW / 4) / 256, 256>>>(x, out + B_ * K_ * D_);
}

// round 15
// speedup vs baseline: 1.1243x; 1.1243x over previous
#include <cuda_runtime.h>
#include <cuda_bf16.h>
#include <math.h>
#include <stdint.h>

#define EPSV  1e-5f
#define SLOPE 0.01f

#define B_    16
#define C_    512
#define NHW   4096
#define D_    128
#define K_    16
#define TN    128
#define TILES 32   // NHW / TN
#define NTILE (B_ * TILES)

// ---------------- PTX helpers ----------------
__device__ __forceinline__ uint32_t smem_to_u32(const void* p) {
  uint32_t a;
  asm("{ .reg .u64 t; cvta.to.shared.u64 t, %1; cvt.u32.u64 %0, t; }" : "=r"(a) : "l"(p));
  return a;
}
__device__ __forceinline__ void ldsm4(uint32_t* r, uint32_t addr) {
  asm volatile("ldmatrix.sync.aligned.m8n8.x4.shared.b16 {%0,%1,%2,%3}, [%4];"
               : "=r"(r[0]), "=r"(r[1]), "=r"(r[2]), "=r"(r[3]) : "r"(addr));
}
__device__ __forceinline__ void mma_bf16(float* d, const uint32_t* a,
                                         uint32_t b0, uint32_t b1) {
  asm volatile(
      "mma.sync.aligned.m16n8k16.row.col.f32.bf16.bf16.f32 "
      "{%0,%1,%2,%3}, {%4,%5,%6,%7}, {%8,%9}, {%0,%1,%2,%3};"
      : "+f"(d[0]), "+f"(d[1]), "+f"(d[2]), "+f"(d[3])
      : "r"(a[0]), "r"(a[1]), "r"(a[2]), "r"(a[3]), "r"(b0), "r"(b1));
}
__device__ __forceinline__ void cpasync16(uint32_t dst, const void* src) {
  asm volatile("cp.async.cg.shared.global [%0], [%1], 16;" :: "r"(dst), "l"(src));
}
__device__ __forceinline__ uint32_t cvt_bf16x2(float hi_elem, float lo_elem) {
  uint32_t r;
  asm("cvt.rn.bf16x2.f32 %0, %1, %2;" : "=r"(r) : "f"(hi_elem), "f"(lo_elem));
  return r;
}
__device__ __forceinline__ unsigned long long ffma2(unsigned long long a,
                                                    unsigned long long b,
                                                    unsigned long long c) {
  unsigned long long d;
  asm("fma.rn.f32x2 %0, %1, %2, %3;" : "=l"(d) : "l"(a), "l"(b), "l"(c));
  return d;
}
__device__ __forceinline__ unsigned long long pack2(float lo, float hi) {
  unsigned long long r;
  asm("mov.b64 %0, {%1, %2};" : "=l"(r) : "f"(lo), "f"(hi));
  return r;
}
__device__ __forceinline__ void unpack2(unsigned long long v, float& lo, float& hi) {
  asm("mov.b64 {%0, %1}, %2;" : "=f"(lo), "=f"(hi) : "l"(v));
}
#define CP_COMMIT() asm volatile("cp.async.commit_group;" ::: "memory")
#define CP_WAIT1()  asm volatile("cp.async.wait_group 1;" ::: "memory")
#define SWZ(x) ((x) ^ (((x) >> 3) & 0x70))

// ---------------- scratch (device globals) ----------------
__device__ __align__(16) float4 g_abn4[C_];   // (sp, tp, g1, h1)
__device__ float g_s2[D_], g_t2[D_];
__device__ float g_c2k[K_];
__device__ __align__(16) __nv_bfloat16 g_wbf_hi[D_ * C_];  // (D,C) K-major
__device__ __align__(16) __nv_bfloat16 g_wbf_lo[D_ * C_];
__device__ float g_spa[B_ * NHW];
__device__ float g_chn[B_ * C_];
__device__ float g_partE[NTILE * K_ * D_];
__device__ float g_partAsum[NTILE * K_];
__device__ float g_encU[B_ * K_ * D_];
__device__ float g_sqp[B_ * 8];
__device__ int   g_ctr;

// ---------------- fold ABN constants (+ work-counter reset) ----------------
__global__ void k_prep_c(const float* __restrict__ pg, const float* __restrict__ pb,
                         const float* __restrict__ pm, const float* __restrict__ pv,
                         const float* __restrict__ a1g, const float* __restrict__ a1b,
                         const float* __restrict__ a1m, const float* __restrict__ a1v) {
  if (blockIdx.x == 0 && threadIdx.x == 0) g_ctr = 0;
  const int c = blockIdx.x * 256 + threadIdx.x;
  if (c < C_) {
    float s = pg[c] * rsqrtf(pv[c] + EPSV);
    float s1 = a1g[c] * rsqrtf(a1v[c] + EPSV);
    g_abn4[c] = make_float4(s, pb[c] - pm[c] * s, s1, a1b[c] - a1m[c] * s1);
  }
}
__global__ void k_prep_d(const float* __restrict__ cb, const float* __restrict__ a2g,
                         const float* __restrict__ a2b, const float* __restrict__ a2m,
                         const float* __restrict__ a2v, const float* __restrict__ cw) {
  const int t = threadIdx.x;
  if (t < D_) {
    float s2 = a2g[t] * rsqrtf(a2v[t] + EPSV);
    g_s2[t] = s2;
    g_t2[t] = cb[t] * s2 + a2b[t] - a2m[t] * s2;
  }
  if (t < K_) {
    float a = 0.f;
    for (int d = 0; d < D_; d++) { float v = cw[t * D_ + d]; a += v * v; }
    g_c2k[t] = a;
  }
}

// ---------------- split conv_w into bf16 hi/lo ----------------
__global__ void k_wsplit(const float* __restrict__ w) {
  const int i = blockIdx.x * 256 + threadIdx.x;
  if (i < D_ * C_) {
    float v = w[i];
    __nv_bfloat16 hi = __float2bfloat16(v);
    g_wbf_hi[i] = hi;
    g_wbf_lo[i] = __float2bfloat16(v - __bfloat162float(hi));
  }
}

// ---------------- fused main kernel: 256 threads, 2 CTAs/SM ----------------
// phase 1 (bytes): A_hi @0 (16K), A_lo @16K, B_hi0 @32K, B_lo0 @48K,
//                  B_hi1 @64K, B_lo1 @80K  (ends 96K)
// phase 2 (floats from 0): X 16896, A @16896 (2048), cw @18944 (2048),
//                  r2 @20992 (2176), sc @23168, c2 @23184,
//                  EP alias @20992 (2048), asp @23200 (128) -> 93312 B
// coef cache @98304 (8KB abn4 + 2KB spa_w) -> untouched by either phase
#define SM_A_HI    0
#define SM_A_LO    16384
#define SM_B_HI(s) (32768 + (s) * 32768)
#define SM_B_LO(s) (32768 + (s) * 32768 + 16384)
#define SM_COEF    98304
#define SMEM_BYTES 108544
#define NCHUNK 8   // C_ / 64
#define NT 256
#define GRID_PERSIST 296

__global__ __launch_bounds__(NT, 2)
void k_main(const float* __restrict__ x, const float* __restrict__ spa_w,
            const float* __restrict__ codewords, const float* __restrict__ scalek) {
  extern __shared__ char smem[];
  __shared__ int s_wk;
  float* smf = reinterpret_cast<float*>(smem);
  const uint32_t smem_base = smem_to_u32(smem);
  const int t = threadIdx.x;
  const int wid = t >> 5, lane = t & 31;
  const int warp_m = wid & 1;      // 2 warps over M=128 (64 rows each)
  const int warp_n = wid >> 1;     // 4 warps over N=128 (32 cols each)
  const int n = t & 127;           // spatial row this thread transforms
  const int half = t >> 7;         // channel half (0/1): 32 channels each
  const int w_d = t >> 1, w_h = t & 1;   // W staging: row d, 64B half

  // persistent coefficient cache (untouched by phase 1/2 regions)
  float4* s_ab = reinterpret_cast<float4*>(smem + SM_COEF);
  float*  s_sw = reinterpret_cast<float*>(smem + SM_COEF + 8192);
  s_ab[t] = g_abn4[t];
  s_ab[t + 256] = g_abn4[t + 256];
  s_sw[t] = spa_w[t];
  s_sw[t + 256] = spa_w[t + 256];
  __syncthreads();

  while (true) {
    if (t == 0) s_wk = atomicAdd(&g_ctr, 1);
    __syncthreads();
    const int wk = s_wk;
    if (wk >= NTILE) break;
    const int b = wk >> 5;
    const int tile = wk & 31;
    const int n0 = tile * TN;
    const float* xb = x + ((size_t)b * C_) * NHW + n0;

    float acc[4][4][4];
#pragma unroll
    for (int i = 0; i < 4; i++)
#pragma unroll
      for (int j = 0; j < 4; j++)
#pragma unroll
        for (int q = 0; q < 4; q++) acc[i][j][q] = 0.f;
    float spa_acc = 0.f;

    auto issue_w = [&](int cc, int s) {
      const __nv_bfloat16* gh = &g_wbf_hi[w_d * C_ + cc * 64 + w_h * 32];
      const __nv_bfloat16* gl = &g_wbf_lo[w_d * C_ + cc * 64 + w_h * 32];
      const uint32_t bh = smem_base + SM_B_HI(s);
      const uint32_t bl = smem_base + SM_B_LO(s);
#pragma unroll
      for (int j = 0; j < 4; j++) {
        const uint32_t bo = SWZ((uint32_t)(w_d * 128 + w_h * 64 + j * 16));
        cpasync16(bh + bo, gh + j * 8);
        cpasync16(bl + bo, gl + j * 8);
      }
    };

    issue_w(0, 0);
    CP_COMMIT();

    for (int cc = 0; cc < NCHUNK; cc++) {
      const int s = cc & 1;

      // ---- fetch + transform -> A tiles (32 channels/thread) ----
      {
        const float* gx = xb + (size_t)(cc * 64 + half * 32) * NHW + n;
        float xcur[32];
#pragma unroll
        for (int j = 0; j < 32; j++) xcur[j] = gx[(size_t)j * NHW];
        const int c0 = cc * 64 + half * 32;
#pragma unroll
        for (int g = 0; g < 4; g++) {
          uint32_t hp[4], lp[4];
#pragma unroll
          for (int jp = 0; jp < 4; jp++) {
            float yv[2];
#pragma unroll
            for (int u = 0; u < 2; u++) {
              const int jj = g * 8 + jp * 2 + u;
              const int c = c0 + jj;
              const float4 cf = s_ab[c];
              float xn = fmaf(xcur[jj], cf.x, cf.y);
              xn = (xn >= 0.f) ? xn : SLOPE * xn;
              spa_acc = fmaf(xn, s_sw[c], spa_acc);
              float y = fmaf(xn, cf.z, cf.w);
              yv[u] = (y >= 0.f) ? y : SLOPE * y;
            }
            const uint32_t b0 = __float_as_uint(yv[0]);
            const uint32_t b1 = __float_as_uint(yv[1]);
            hp[jp] = __byte_perm(b0, b1, 0x7632);
            const float lo0 = yv[0] - __uint_as_float(b0 & 0xFFFF0000u);
            const float lo1 = yv[1] - __uint_as_float(b1 & 0xFFFF0000u);
            lp[jp] = cvt_bf16x2(lo1, lo0);
          }
          const uint32_t bo = SWZ((uint32_t)(n * 128 + (half * 32 + g * 8) * 2));
          *reinterpret_cast<uint4*>(smem + SM_A_HI + bo) = make_uint4(hp[0], hp[1], hp[2], hp[3]);
          *reinterpret_cast<uint4*>(smem + SM_A_LO + bo) = make_uint4(lp[0], lp[1], lp[2], lp[3]);
        }
      }
      __syncthreads();     // A ready (prev mma finished before prior barrier)

      if (cc + 1 < NCHUNK) issue_w(cc + 1, s ^ 1);
      CP_COMMIT();
      CP_WAIT1();          // B[s] resident

      // ---- tensor-core GEMM (2M x 4N warps, 64x32 each), pass-major ----
#pragma unroll
      for (int ks = 0; ks < 4; ks++) {
        uint32_t aH[4][4], aL[4][4];
#pragma unroll
        for (int mt = 0; mt < 4; mt++) {
          const uint32_t row = warp_m * 64 + mt * 16 + (lane & 15);
          const uint32_t colb = ks * 32 + ((lane >> 4) << 4);
          const uint32_t sw = SWZ(row * 128 + colb);
          ldsm4(aH[mt], smem_base + SM_A_HI + sw);
          ldsm4(aL[mt], smem_base + SM_A_LO + sw);
        }
        uint32_t bh[2][4], bl[2][4];
#pragma unroll
        for (int p = 0; p < 2; p++) {
          const uint32_t d = warp_n * 32 + p * 16 + (lane & 7) + ((lane >> 4) & 1) * 8;
          const uint32_t colb = ks * 32 + (((lane >> 3) & 1) << 4);
          const uint32_t sw = SWZ(d * 128 + colb);
          ldsm4(bh[p], smem_base + SM_B_HI(s) + sw);
          ldsm4(bl[p], smem_base + SM_B_LO(s) + sw);
        }
#pragma unroll
        for (int p = 0; p < 2; p++) {
          // pass 1: hi*hi (mt-major: 4 independent accumulators back-to-back)
#pragma unroll
          for (int mt = 0; mt < 4; mt++) mma_bf16(acc[mt][2 * p],     aH[mt], bh[p][0], bh[p][1]);
#pragma unroll
          for (int mt = 0; mt < 4; mt++) mma_bf16(acc[mt][2 * p + 1], aH[mt], bh[p][2], bh[p][3]);
          // pass 2: hi*lo
#pragma unroll
          for (int mt = 0; mt < 4; mt++) mma_bf16(acc[mt][2 * p],     aH[mt], bl[p][0], bl[p][1]);
#pragma unroll
          for (int mt = 0; mt < 4; mt++) mma_bf16(acc[mt][2 * p + 1], aH[mt], bl[p][2], bl[p][3]);
          // pass 3: lo*hi
#pragma unroll
          for (int mt = 0; mt < 4; mt++) mma_bf16(acc[mt][2 * p],     aL[mt], bh[p][0], bh[p][1]);
#pragma unroll
          for (int mt = 0; mt < 4; mt++) mma_bf16(acc[mt][2 * p + 1], aL[mt], bh[p][2], bh[p][3]);
        }
      }
      __syncthreads();     // mma done before next transform overwrites A
    }

    // ---- spatial SE combine (2 partials per n) + sigmoid ----
    smf[t] = spa_acc;
    __syncthreads();
    if (t < TN) {
      const float sps = smf[t] + smf[128 + t];
      g_spa[b * NHW + n0 + t] = 1.f / (1.f + __expf(-sps));
    }
    __syncthreads();

    // ---- phase 2 smem layout (floats) ----
    float* s_X  = smf;           // 128 x 132
    float* s_A  = smf + 16896;   // 128 x 16
    float* s_cw = smf + 18944;   // 16 x 128
    float* s_r2 = smf + 20992;   // 17 x 128
    float* s_sc = smf + 23168;
    float* s_c2 = smf + 23184;

    // ---- epilogue: acc -> abn2 + leaky -> s_X (each warp 64 rows x 32 cols) ----
    {
      const int quad = lane >> 2, qp = lane & 3;
#pragma unroll
      for (int mt = 0; mt < 4; mt++) {
        const int r0 = warp_m * 64 + mt * 16 + quad;
#pragma unroll
        for (int nt = 0; nt < 4; nt++) {
          const int cd = warp_n * 32 + nt * 8 + qp * 2;
          const float s2a = g_s2[cd], s2b = g_s2[cd + 1];
          const float t2a = g_t2[cd], t2b = g_t2[cd + 1];
          float z0 = fmaf(acc[mt][nt][0], s2a, t2a); z0 = (z0 >= 0.f) ? z0 : SLOPE * z0;
          float z1 = fmaf(acc[mt][nt][1], s2b, t2b); z1 = (z1 >= 0.f) ? z1 : SLOPE * z1;
          float z2 = fmaf(acc[mt][nt][2], s2a, t2a); z2 = (z2 >= 0.f) ? z2 : SLOPE * z2;
          float z3 = fmaf(acc[mt][nt][3], s2b, t2b); z3 = (z3 >= 0.f) ? z3 : SLOPE * z3;
          *reinterpret_cast<float2*>(&s_X[r0 * 132 + cd])       = make_float2(z0, z1);
          *reinterpret_cast<float2*>(&s_X[(r0 + 8) * 132 + cd]) = make_float2(z2, z3);
        }
      }
    }
#pragma unroll
    for (int i = 0; i < 8; i++) s_cw[t * 8 + i] = codewords[t * 8 + i];
    if (t < K_) { s_sc[t] = scalek[t]; s_c2[t] = g_c2k[t]; }
    __syncthreads();

    // ---- scaled-L2 softmax assignment A (2 threads per position, 64 dims each) ----
    {
      const int nn = t & 127;
      const int q = t >> 7;
      const float* xr = &s_X[nn * 132 + q * 64];
      unsigned long long px2p = 0ull;
      unsigned long long pxcp[16];
#pragma unroll
      for (int k = 0; k < 16; k++) pxcp[k] = 0ull;
#pragma unroll 4
      for (int ch = 0; ch < 16; ch++) {
        const ulonglong2 xp = *reinterpret_cast<const ulonglong2*>(xr + ch * 4);
        px2p = ffma2(xp.x, xp.x, px2p);
        px2p = ffma2(xp.y, xp.y, px2p);
        const int dd = q * 64 + ch * 4;
#pragma unroll
        for (int k = 0; k < 16; k++) {
          const ulonglong2 cp = *reinterpret_cast<const ulonglong2*>(&s_cw[k * 128 + dd]);
          pxcp[k] = ffma2(xp.x, cp.x, pxcp[k]);
          pxcp[k] = ffma2(xp.y, cp.y, pxcp[k]);
        }
      }
      float px2, pxc[16];
      {
        float lo, hi;
        unpack2(px2p, lo, hi);
        px2 = lo + hi;
#pragma unroll
        for (int k = 0; k < 16; k++) { unpack2(pxcp[k], lo, hi); pxc[k] = lo + hi; }
      }
      if (q) {
        s_r2[nn] = px2;
#pragma unroll
        for (int k = 0; k < 16; k++) s_r2[128 + k * 128 + nn] = pxc[k];
      }
      __syncthreads();
      if (!q) {
        float x2 = px2 + s_r2[nn];
        float sl[16];
        float m = -1e30f;
#pragma unroll
        for (int k = 0; k < 16; k++) {
          float xc = pxc[k] + s_r2[128 + k * 128 + nn];
          float v = s_sc[k] * (x2 - 2.f * xc + s_c2[k]);
          sl[k] = v;
          m = fmaxf(m, v);
        }
        float ssum = 0.f;
#pragma unroll
        for (int k = 0; k < 16; k++) { float e2 = __expf(sl[k] - m); sl[k] = e2; ssum += e2; }
        const float inv = 1.f / ssum;
#pragma unroll
        for (int k = 0; k < 16; k++) s_A[nn * 16 + k] = sl[k] * inv;
      }
      __syncthreads();
    }

    // ---- partial E = A^T @ X (broadcast form, f32x2; thread = (d, n-group)) ----
    {
      const int d = t & 127;
      const int ng = t >> 7;           // 0..1, 64 n's each
      unsigned long long e2[8];
#pragma unroll
      for (int j = 0; j < 8; j++) e2[j] = 0ull;
      const int nb0 = ng * 64;
      for (int nn = nb0; nn < nb0 + 64; nn++) {
        const float xv = s_X[nn * 132 + d];
        const unsigned long long xvp = pack2(xv, xv);
        const ulonglong2* ar = reinterpret_cast<const ulonglong2*>(&s_A[nn * 16]);
#pragma unroll
        for (int j2 = 0; j2 < 4; j2++) {
          const ulonglong2 ap = ar[j2];
          e2[j2 * 2]     = ffma2(ap.x, xvp, e2[j2 * 2]);
          e2[j2 * 2 + 1] = ffma2(ap.y, xvp, e2[j2 * 2 + 1]);
        }
      }
      float e[16];
#pragma unroll
      for (int j = 0; j < 8; j++) unpack2(e2[j], e[2 * j], e[2 * j + 1]);
      float* s_EP  = smf + 20992;     // alias s_r2 (softmax done)
      float* s_asp = smf + 23200;     // 128 floats
      if (ng == 1) {
#pragma unroll
        for (int k = 0; k < 16; k++) s_EP[k * 128 + d] = e[k];
      }
      if (t < 128) {                   // ng == 0: also compute asum partials
        const int kk = t >> 3, seg = t & 7;
        float a = 0.f;
        for (int nn = seg * 16; nn < seg * 16 + 16; nn++) a += s_A[nn * 16 + kk];
        s_asp[t] = a;
      }
      __syncthreads();
      if (ng == 0) {
#pragma unroll
        for (int k = 0; k < 16; k++) {
          e[k] += s_EP[k * 128 + d];
          g_partE[(wk * K_ + k) * D_ + d] = e[k];
        }
      }
      if (t < 16) {
        float a = 0.f;
#pragma unroll
        for (int j = 0; j < 8; j++) a += s_asp[t * 8 + j];
        g_partAsum[wk * K_ + t] = a;
      }
    }
    __syncthreads();   // protect smem before next tile
  }
}

// ---------------- stage 1 reduce: grid 128 = b x 8 slices ----------------
__global__ void k_red1(const float* __restrict__ codewords) {
  __shared__ float s_as2[2];
  __shared__ float s_red[256];
  const int blk = blockIdx.x;
  const int b = blk >> 3, slice = blk & 7;
  const int t = threadIdx.x;
  const int idx = slice * 256 + t;        // 0..2047 within this b
  if (t < 2) {
    const int k = slice * 2 + t;
    float a = 0.f;
    for (int tile = 0; tile < TILES; tile++)
      a += g_partAsum[(b * TILES + tile) * K_ + k];
    s_as2[t] = a;
  }
  __syncthreads();
  float e = 0.f;
  const int base = b * TILES * 2048 + idx;
  for (int tile = 0; tile < TILES; tile++) e += g_partE[base + tile * 2048];
  e -= s_as2[t >> 7] * codewords[idx];    // idx == k*128 + d in (K,D) layout
  g_encU[b * 2048 + idx] = e;
  s_red[t] = e * e;
  __syncthreads();
  for (int s = 128; s > 0; s >>= 1) {
    if (t < s) s_red[t] += s_red[t + s];
    __syncthreads();
  }
  if (t == 0) g_sqp[blk] = s_red[0];
}

// ---------------- write normalized enc to d_out ----------------
__global__ void k_encw(float* __restrict__ out_enc) {
  const int idx = blockIdx.x * 256 + threadIdx.x;  // 32768 total
  const int b = idx >> 11;
  float s = 0.f;
#pragma unroll
  for (int j = 0; j < 8; j++) s += g_sqp[b * 8 + j];
  const float rn = 1.f / fmaxf(sqrtf(s), 1e-12f);
  out_enc[idx] = g_encU[idx] * rn;
}

// ---------------- channel SE (norm folded in post-dot) ----------------
__global__ __launch_bounds__(256)
void k_chse(const float* __restrict__ se_w, const float* __restrict__ se_b) {
  __shared__ float sw[2048];
  __shared__ float s_rn[16];
  const int c = blockIdx.x;
  const int t = threadIdx.x;
  if (t < 16) {
    float s = 0.f;
#pragma unroll
    for (int j = 0; j < 8; j++) s += g_sqp[t * 8 + j];
    s_rn[t] = 1.f / fmaxf(sqrtf(s), 1e-12f);
  }
  const float* wr = se_w + (size_t)c * 2048;
#pragma unroll
  for (int i = 0; i < 8; i++) sw[t + i * 256] = wr[t + i * 256];
  __syncthreads();
  const int w = t >> 5, lane = t & 31;
  const float bias = se_b[c];
#pragma unroll
  for (int bb = 0; bb < 2; bb++) {
    const int b = w * 2 + bb;
    const float* er = g_encU + b * 2048;
    float p = 0.f;
#pragma unroll 8
    for (int i = 0; i < 64; i++) {
      const int idx = lane + (i << 5);
      p = fmaf(er[idx], sw[idx], p);
    }
#pragma unroll
    for (int o = 16; o > 0; o >>= 1) p += __shfl_xor_sync(0xffffffffu, p, o);
    if (lane == 0)
      g_chn[b * C_ + c] = 1.f / (1.f + __expf(-fmaf(p, s_rn[b], bias)));
  }
}

// ---------------- final gating: out = x * spa_se * chn_se ----------------
__global__ void k_out(const float* __restrict__ x, float* __restrict__ out) {
  const int i = blockIdx.x * 256 + threadIdx.x;
  float4 v = reinterpret_cast<const float4*>(x)[i];
  const int b = i >> 19;
  const int rem = i & 524287;
  const int c = rem >> 10;
  const int n4 = rem & 1023;
  const float4 sp = reinterpret_cast<const float4*>(g_spa)[b * 1024 + n4];
  const float ch = g_chn[b * C_ + c];
  float4 o;
  o.x = v.x * sp.x * ch;
  o.y = v.y * sp.y * ch;
  o.z = v.z * sp.z * ch;
  o.w = v.w * sp.w * ch;
  reinterpret_cast<float4*>(out)[i] = o;
}

extern "C" void kernel_launch(void* const* d_in, const int* in_sizes, int n_in,
                              void* d_out, int out_size) {
  const float* x    = (const float*)d_in[0];
  const float* pg   = (const float*)d_in[1];
  const float* pb   = (const float*)d_in[2];
  const float* pm   = (const float*)d_in[3];
  const float* pv   = (const float*)d_in[4];
  const float* a1g  = (const float*)d_in[5];
  const float* a1b  = (const float*)d_in[6];
  const float* a1m  = (const float*)d_in[7];
  const float* a1v  = (const float*)d_in[8];
  const float* cwv  = (const float*)d_in[9];   // conv_w (D, C)
  const float* cb   = (const float*)d_in[10];
  const float* a2g  = (const float*)d_in[11];
  const float* a2b  = (const float*)d_in[12];
  const float* a2m  = (const float*)d_in[13];
  const float* a2v  = (const float*)d_in[14];
  const float* cdw  = (const float*)d_in[15];  // codewords (K, D)
  const float* sck  = (const float*)d_in[16];  // scale (K,)
  const float* sew  = (const float*)d_in[17];  // se_w (C, K*D)
  const float* seb  = (const float*)d_in[18];
  const float* spw  = (const float*)d_in[19];  // spa_w (C,)
  float* out = (float*)d_out;

  cudaFuncSetAttribute(k_main, cudaFuncAttributeMaxDynamicSharedMemorySize, SMEM_BYTES);

  k_prep_c<<<2, 256>>>(pg, pb, pm, pv, a1g, a1b, a1m, a1v);
  k_prep_d<<<1, 128>>>(cb, a2g, a2b, a2m, a2v, cdw);
  k_wsplit<<<(D_ * C_ + 255) / 256, 256>>>(cwv);
  k_main<<<GRID_PERSIST, NT, SMEM_BYTES>>>(x, spw, cdw, sck);
  k_red1<<<128, 256>>>(cdw);
  k_encw<<<128, 256>>>(out);
  k_chse<<<C_, 256>>>(sew, seb);
  k_out<<<(B_ * C_ * NHW / 4) / 256, 256>>>(x, out + B_ * K_ * D_);
}

// round 16
// speedup vs baseline: 1.2504x; 1.1121x over previous
#include <cuda_runtime.h>
#include <cuda_bf16.h>
#include <math.h>
#include <stdint.h>

#define EPSV  1e-5f
#define SLOPE 0.01f

#define B_    16
#define C_    512
#define NHW   4096
#define D_    128
#define K_    16
#define TN    128
#define TILES 32   // NHW / TN
#define NTILE (B_ * TILES)

// ---------------- PTX helpers ----------------
__device__ __forceinline__ uint32_t smem_to_u32(const void* p) {
  uint32_t a;
  asm("{ .reg .u64 t; cvta.to.shared.u64 t, %1; cvt.u32.u64 %0, t; }" : "=r"(a) : "l"(p));
  return a;
}
__device__ __forceinline__ void ldsm4(uint32_t* r, uint32_t addr) {
  asm volatile("ldmatrix.sync.aligned.m8n8.x4.shared.b16 {%0,%1,%2,%3}, [%4];"
               : "=r"(r[0]), "=r"(r[1]), "=r"(r[2]), "=r"(r[3]) : "r"(addr));
}
__device__ __forceinline__ void mma_bf16(float* d, const uint32_t* a,
                                         uint32_t b0, uint32_t b1) {
  asm volatile(
      "mma.sync.aligned.m16n8k16.row.col.f32.bf16.bf16.f32 "
      "{%0,%1,%2,%3}, {%4,%5,%6,%7}, {%8,%9}, {%0,%1,%2,%3};"
      : "+f"(d[0]), "+f"(d[1]), "+f"(d[2]), "+f"(d[3])
      : "r"(a[0]), "r"(a[1]), "r"(a[2]), "r"(a[3]), "r"(b0), "r"(b1));
}
__device__ __forceinline__ void cpasync16(uint32_t dst, const void* src) {
  asm volatile("cp.async.cg.shared.global [%0], [%1], 16;" :: "r"(dst), "l"(src));
}
__device__ __forceinline__ uint32_t cvt_bf16x2(float hi_elem, float lo_elem) {
  uint32_t r;
  asm("cvt.rn.bf16x2.f32 %0, %1, %2;" : "=r"(r) : "f"(hi_elem), "f"(lo_elem));
  return r;
}
__device__ __forceinline__ unsigned long long ffma2(unsigned long long a,
                                                    unsigned long long b,
                                                    unsigned long long c) {
  unsigned long long d;
  asm("fma.rn.f32x2 %0, %1, %2, %3;" : "=l"(d) : "l"(a), "l"(b), "l"(c));
  return d;
}
__device__ __forceinline__ unsigned long long pack2(float lo, float hi) {
  unsigned long long r;
  asm("mov.b64 %0, {%1, %2};" : "=l"(r) : "f"(lo), "f"(hi));
  return r;
}
__device__ __forceinline__ void unpack2(unsigned long long v, float& lo, float& hi) {
  asm("mov.b64 {%0, %1}, %2;" : "=f"(lo), "=f"(hi) : "l"(v));
}
#define CP_COMMIT() asm volatile("cp.async.commit_group;" ::: "memory")
#define CP_WAIT1()  asm volatile("cp.async.wait_group 1;" ::: "memory")
#define SWZ(x) ((x) ^ (((x) >> 3) & 0x70))

// ---------------- scratch (device globals) ----------------
__device__ __align__(16) float4 g_abn4[C_];   // (sp, tp, g1, h1)
__device__ float g_s2[D_], g_t2[D_];
__device__ float g_c2k[K_];
__device__ __align__(16) __nv_bfloat16 g_wbf_hi[D_ * C_];  // (D,C) K-major
__device__ __align__(16) __nv_bfloat16 g_wbf_lo[D_ * C_];
__device__ float g_spa[B_ * NHW];
__device__ float g_chn[B_ * C_];
__device__ float g_partE[NTILE * K_ * D_];
__device__ float g_partAsum[NTILE * K_];
__device__ float g_encU[B_ * K_ * D_];   // unnormalized enc
__device__ float g_sqp[B_ * 8];          // per-slice sumsq partials
__device__ int   g_ctr;

// ---------------- fold ABN constants (+ work-counter reset) ----------------
__global__ void k_prep_c(const float* __restrict__ pg, const float* __restrict__ pb,
                         const float* __restrict__ pm, const float* __restrict__ pv,
                         const float* __restrict__ a1g, const float* __restrict__ a1b,
                         const float* __restrict__ a1m, const float* __restrict__ a1v) {
  if (blockIdx.x == 0 && threadIdx.x == 0) g_ctr = 0;
  const int c = blockIdx.x * 256 + threadIdx.x;
  if (c < C_) {
    float s = pg[c] * rsqrtf(pv[c] + EPSV);
    float s1 = a1g[c] * rsqrtf(a1v[c] + EPSV);
    g_abn4[c] = make_float4(s, pb[c] - pm[c] * s, s1, a1b[c] - a1m[c] * s1);
  }
}
__global__ void k_prep_d(const float* __restrict__ cb, const float* __restrict__ a2g,
                         const float* __restrict__ a2b, const float* __restrict__ a2m,
                         const float* __restrict__ a2v, const float* __restrict__ cw) {
  const int t = threadIdx.x;
  if (t < D_) {
    float s2 = a2g[t] * rsqrtf(a2v[t] + EPSV);
    g_s2[t] = s2;
    g_t2[t] = cb[t] * s2 + a2b[t] - a2m[t] * s2;
  }
  if (t < K_) {
    float a = 0.f;
    for (int d = 0; d < D_; d++) { float v = cw[t * D_ + d]; a += v * v; }
    g_c2k[t] = a;
  }
}

// ---------------- split conv_w into bf16 hi/lo ----------------
__global__ void k_wsplit(const float* __restrict__ w) {
  const int i = blockIdx.x * 256 + threadIdx.x;
  if (i < D_ * C_) {
    float v = w[i];
    __nv_bfloat16 hi = __float2bfloat16(v);
    g_wbf_hi[i] = hi;
    g_wbf_lo[i] = __float2bfloat16(v - __bfloat162float(hi));
  }
}

// ---------------- fused main kernel (R13 best configuration) ----------------
#define SM_A_HI(s) ((s) * 32768)
#define SM_A_LO(s) ((s) * 32768 + 16384)
#define SM_B_HI(s) (65536 + (s) * 32768)
#define SM_B_LO(s) (65536 + (s) * 32768 + 16384)
#define SM_COEF    131072
#define SMEM_BYTES 141312
#define NCHUNK 8   // C_ / 64
#define NT 512
#define GRID_PERSIST 148

__global__ __launch_bounds__(NT)
void k_main(const float* __restrict__ x, const float* __restrict__ spa_w,
            const float* __restrict__ codewords, const float* __restrict__ scalek) {
  extern __shared__ char smem[];
  __shared__ int s_wk;
  float* smf = reinterpret_cast<float*>(smem);
  const uint32_t smem_base = smem_to_u32(smem);
  const int t = threadIdx.x;
  const int wid = t >> 5, lane = t & 31;
  const int warp_m = wid & 3;
  const int warp_n = wid >> 2;
  const int n = t & 127;
  const int cg = t >> 7;
  const int w_d = t >> 2, w_q = t & 3;

  // persistent coefficient cache
  float4* s_ab = reinterpret_cast<float4*>(smem + SM_COEF);
  float*  s_sw = reinterpret_cast<float*>(smem + SM_COEF + 8192);
  s_ab[t] = g_abn4[t];
  s_sw[t] = spa_w[t];
  __syncthreads();

  while (true) {
    if (t == 0) s_wk = atomicAdd(&g_ctr, 1);
    __syncthreads();
    const int wk = s_wk;
    if (wk >= NTILE) break;
    const int b = wk >> 5;
    const int tile = wk & 31;
    const int n0 = tile * TN;
    const float* xb = x + ((size_t)b * C_) * NHW + n0;

    float acc[2][4][4];
#pragma unroll
    for (int i = 0; i < 2; i++)
#pragma unroll
      for (int j = 0; j < 4; j++)
#pragma unroll
        for (int q = 0; q < 4; q++) acc[i][j][q] = 0.f;
    float spa_acc = 0.f;
    float xcur[16];

    auto issue_w = [&](int cc, int s) {
      const __nv_bfloat16* gh = &g_wbf_hi[w_d * C_ + cc * 64 + w_q * 16];
      const __nv_bfloat16* gl = &g_wbf_lo[w_d * C_ + cc * 64 + w_q * 16];
      const uint32_t bh = smem_base + SM_B_HI(s);
      const uint32_t bl = smem_base + SM_B_LO(s);
#pragma unroll
      for (int j = 0; j < 2; j++) {
        const uint32_t bo = SWZ((uint32_t)(w_d * 128 + w_q * 32 + j * 16));
        cpasync16(bh + bo, gh + j * 8);
        cpasync16(bl + bo, gl + j * 8);
      }
    };
    auto fetch_x = [&](int cc) {
      const float* gx = xb + (size_t)(cc * 64 + cg * 16) * NHW + n;
#pragma unroll
      for (int j = 0; j < 16; j++) xcur[j] = gx[(size_t)j * NHW];
    };

    issue_w(0, 0);
    CP_COMMIT();
    fetch_x(0);

    for (int cc = 0; cc < NCHUNK; cc++) {
      const int s = cc & 1;

      // ---- transform xcur -> A[s] hi/lo tiles ----
      const int c0 = cc * 64 + cg * 16;
#pragma unroll
      for (int g = 0; g < 2; g++) {
        uint32_t hp[4], lp[4];
#pragma unroll
        for (int jp = 0; jp < 4; jp++) {
          float yv[2];
#pragma unroll
          for (int u = 0; u < 2; u++) {
            const int jj = g * 8 + jp * 2 + u;
            const int c = c0 + jj;
            const float4 cf = s_ab[c];
            float xn = fmaf(xcur[jj], cf.x, cf.y);
            xn = (xn >= 0.f) ? xn : SLOPE * xn;
            spa_acc = fmaf(xn, s_sw[c], spa_acc);
            float y = fmaf(xn, cf.z, cf.w);
            yv[u] = (y >= 0.f) ? y : SLOPE * y;
          }
          const uint32_t b0 = __float_as_uint(yv[0]);
          const uint32_t b1 = __float_as_uint(yv[1]);
          hp[jp] = __byte_perm(b0, b1, 0x7632);
          const float lo0 = yv[0] - __uint_as_float(b0 & 0xFFFF0000u);
          const float lo1 = yv[1] - __uint_as_float(b1 & 0xFFFF0000u);
          lp[jp] = cvt_bf16x2(lo1, lo0);
        }
        const uint32_t bo = SWZ((uint32_t)(n * 128 + (cg * 16 + g * 8) * 2));
        *reinterpret_cast<uint4*>(smem + SM_A_HI(s) + bo) = make_uint4(hp[0], hp[1], hp[2], hp[3]);
        *reinterpret_cast<uint4*>(smem + SM_A_LO(s) + bo) = make_uint4(lp[0], lp[1], lp[2], lp[3]);
      }

      __syncthreads();     // A[s] ready; all mma(cc-1) done

      if (cc + 1 < NCHUNK) issue_w(cc + 1, s ^ 1);
      CP_COMMIT();
      CP_WAIT1();          // B[s] resident

      if (cc + 1 < NCHUNK) fetch_x(cc + 1);

      // ---- tensor-core GEMM, pass-major issue order (RAW distance 4) ----
#pragma unroll
      for (int ks = 0; ks < 4; ks++) {
        uint32_t aH[2][4], aL[2][4];
#pragma unroll
        for (int mt = 0; mt < 2; mt++) {
          const uint32_t row = warp_m * 32 + mt * 16 + (lane & 15);
          const uint32_t colb = ks * 32 + ((lane >> 4) << 4);
          const uint32_t sw = SWZ(row * 128 + colb);
          ldsm4(aH[mt], smem_base + SM_A_HI(s) + sw);
          ldsm4(aL[mt], smem_base + SM_A_LO(s) + sw);
        }
#pragma unroll
        for (int p = 0; p < 2; p++) {
          const uint32_t d = warp_n * 32 + p * 16 + (lane & 7) + ((lane >> 4) & 1) * 8;
          const uint32_t colb = ks * 32 + (((lane >> 3) & 1) << 4);
          const uint32_t sw = SWZ(d * 128 + colb);
          uint32_t bh[4], bl[4];
          ldsm4(bh, smem_base + SM_B_HI(s) + sw);
          ldsm4(bl, smem_base + SM_B_LO(s) + sw);
          // pass 1: hi*hi (4 independent accumulators)
          mma_bf16(acc[0][2 * p],     aH[0], bh[0], bh[1]);
          mma_bf16(acc[1][2 * p],     aH[1], bh[0], bh[1]);
          mma_bf16(acc[0][2 * p + 1], aH[0], bh[2], bh[3]);
          mma_bf16(acc[1][2 * p + 1], aH[1], bh[2], bh[3]);
          // pass 2: hi*lo
          mma_bf16(acc[0][2 * p],     aH[0], bl[0], bl[1]);
          mma_bf16(acc[1][2 * p],     aH[1], bl[0], bl[1]);
          mma_bf16(acc[0][2 * p + 1], aH[0], bl[2], bl[3]);
          mma_bf16(acc[1][2 * p + 1], aH[1], bl[2], bl[3]);
          // pass 3: lo*hi
          mma_bf16(acc[0][2 * p],     aL[0], bh[0], bh[1]);
          mma_bf16(acc[1][2 * p],     aL[1], bh[0], bh[1]);
          mma_bf16(acc[0][2 * p + 1], aL[0], bh[2], bh[3]);
          mma_bf16(acc[1][2 * p + 1], aL[1], bh[2], bh[3]);
        }
      }
      // no trailing barrier: next transform writes A[s^1] (disjoint)
    }

    // ---- spatial SE combine + sigmoid ----
    smf[t] = spa_acc;
    __syncthreads();
    if (t < TN) {
      const float sps = smf[t] + smf[128 + t] + smf[256 + t] + smf[384 + t];
      g_spa[b * NHW + n0 + t] = 1.f / (1.f + __expf(-sps));
    }
    __syncthreads();

    // ---- phase 2 smem layout ----
    float* s_X  = smf;           // 128 x 132
    float* s_A  = smf + 16896;   // 128 x 16
    float* s_cw = smf + 18944;   // 16 x 128
    float* s_r2 = smf + 20992;   // 3 x 2176 (softmax partials)
    float* s_sc = smf + 27520;
    float* s_c2 = smf + 27536;

    // ---- epilogue: acc -> abn2 + leaky -> s_X ----
    {
      const int quad = lane >> 2, qp = lane & 3;
#pragma unroll
      for (int mt = 0; mt < 2; mt++) {
        const int r0 = warp_m * 32 + mt * 16 + quad;
#pragma unroll
        for (int nt = 0; nt < 4; nt++) {
          const int cd = warp_n * 32 + nt * 8 + qp * 2;
          const float s2a = g_s2[cd], s2b = g_s2[cd + 1];
          const float t2a = g_t2[cd], t2b = g_t2[cd + 1];
          float z0 = fmaf(acc[mt][nt][0], s2a, t2a); z0 = (z0 >= 0.f) ? z0 : SLOPE * z0;
          float z1 = fmaf(acc[mt][nt][1], s2b, t2b); z1 = (z1 >= 0.f) ? z1 : SLOPE * z1;
          float z2 = fmaf(acc[mt][nt][2], s2a, t2a); z2 = (z2 >= 0.f) ? z2 : SLOPE * z2;
          float z3 = fmaf(acc[mt][nt][3], s2b, t2b); z3 = (z3 >= 0.f) ? z3 : SLOPE * z3;
          *reinterpret_cast<float2*>(&s_X[r0 * 132 + cd])       = make_float2(z0, z1);
          *reinterpret_cast<float2*>(&s_X[(r0 + 8) * 132 + cd]) = make_float2(z2, z3);
        }
      }
    }
#pragma unroll
    for (int i = 0; i < 4; i++) s_cw[t * 4 + i] = codewords[t * 4 + i];
    if (t < K_) { s_sc[t] = scalek[t]; s_c2[t] = g_c2k[t]; }
    __syncthreads();

    // ---- scaled-L2 softmax assignment A (4 threads per position, f32x2) ----
    {
      const int nn = t & 127;
      const int q = t >> 7;
      const float* xr = &s_X[nn * 132 + q * 32];
      unsigned long long px2p = 0ull;
      unsigned long long pxcp[16];
#pragma unroll
      for (int k = 0; k < 16; k++) pxcp[k] = 0ull;
#pragma unroll
      for (int ch = 0; ch < 8; ch++) {
        const ulonglong2 xp = *reinterpret_cast<const ulonglong2*>(xr + ch * 4);
        px2p = ffma2(xp.x, xp.x, px2p);
        px2p = ffma2(xp.y, xp.y, px2p);
        const int dd = q * 32 + ch * 4;
#pragma unroll
        for (int k = 0; k < 16; k++) {
          const ulonglong2 cp = *reinterpret_cast<const ulonglong2*>(&s_cw[k * 128 + dd]);
          pxcp[k] = ffma2(xp.x, cp.x, pxcp[k]);
          pxcp[k] = ffma2(xp.y, cp.y, pxcp[k]);
        }
      }
      float px2, pxc[16];
      {
        float lo, hi;
        unpack2(px2p, lo, hi);
        px2 = lo + hi;
#pragma unroll
        for (int k = 0; k < 16; k++) { unpack2(pxcp[k], lo, hi); pxc[k] = lo + hi; }
      }
      if (q) {
        float* sr = s_r2 + (q - 1) * 2176;
        sr[nn] = px2;
#pragma unroll
        for (int k = 0; k < 16; k++) sr[128 + k * 128 + nn] = pxc[k];
      }
      __syncthreads();
      if (!q) {
        float x2 = px2 + s_r2[nn] + s_r2[2176 + nn] + s_r2[4352 + nn];
        float sl[16];
        float m = -1e30f;
#pragma unroll
        for (int k = 0; k < 16; k++) {
          float xc = pxc[k] + s_r2[128 + k * 128 + nn] + s_r2[2304 + k * 128 + nn] +
                     s_r2[4480 + k * 128 + nn];
          float v = s_sc[k] * (x2 - 2.f * xc + s_c2[k]);
          sl[k] = v;
          m = fmaxf(m, v);
        }
        float ssum = 0.f;
#pragma unroll
        for (int k = 0; k < 16; k++) { float e2 = __expf(sl[k] - m); sl[k] = e2; ssum += e2; }
        const float inv = 1.f / ssum;
#pragma unroll
        for (int k = 0; k < 16; k++) s_A[nn * 16 + k] = sl[k] * inv;
      }
      __syncthreads();
    }

    // ---- partial E = A^T @ X (broadcast form, f32x2) ----
    {
      const int d = t & 127;
      const int ng = t >> 7;           // 0..3, 32 n's each
      unsigned long long e2[8];
#pragma unroll
      for (int j = 0; j < 8; j++) e2[j] = 0ull;
      const int nb0 = ng * 32;
      for (int nn = nb0; nn < nb0 + 32; nn++) {
        const float xv = s_X[nn * 132 + d];
        const unsigned long long xvp = pack2(xv, xv);
        const ulonglong2* ar = reinterpret_cast<const ulonglong2*>(&s_A[nn * 16]);
#pragma unroll
        for (int j2 = 0; j2 < 4; j2++) {
          const ulonglong2 ap = ar[j2];
          e2[j2 * 2]     = ffma2(ap.x, xvp, e2[j2 * 2]);
          e2[j2 * 2 + 1] = ffma2(ap.y, xvp, e2[j2 * 2 + 1]);
        }
      }
      float e[16];
#pragma unroll
      for (int j = 0; j < 8; j++) unpack2(e2[j], e[2 * j], e[2 * j + 1]);
      float* s_EP  = smf + 20992;     // alias s_r2 (softmax done)
      float* s_asp = smf + 25088;     // 128 floats
      if (ng >= 2) {
#pragma unroll
        for (int k = 0; k < 16; k++) s_EP[(ng - 2) * 2048 + k * 128 + d] = e[k];
      }
      if (t < 128) {                   // ng == 0: also compute asum partials
        const int kk = t >> 3, seg = t & 7;
        float a = 0.f;
        for (int nn = seg * 16; nn < seg * 16 + 16; nn++) a += s_A[nn * 16 + kk];
        s_asp[t] = a;
      }
      __syncthreads();
      if (ng < 2) {
#pragma unroll
        for (int k = 0; k < 16; k++) e[k] += s_EP[ng * 2048 + k * 128 + d];
      }
      if (t < 16) {
        float a = 0.f;
#pragma unroll
        for (int j = 0; j < 8; j++) a += s_asp[t * 8 + j];
        g_partAsum[wk * K_ + t] = a;
      }
      __syncthreads();
      if (ng == 1) {
#pragma unroll
        for (int k = 0; k < 16; k++) s_EP[k * 128 + d] = e[k];
      }
      __syncthreads();
      if (ng == 0) {
#pragma unroll
        for (int k = 0; k < 16; k++) {
          e[k] += s_EP[k * 128 + d];
          g_partE[(wk * K_ + k) * D_ + d] = e[k];
        }
      }
    }
    __syncthreads();   // protect smem before next tile
  }
}

// ---------------- stage 1 reduce: grid 128 = b x 8 slices ----------------
__global__ void k_red1(const float* __restrict__ codewords) {
  __shared__ float s_as2[2];
  __shared__ float s_red[256];
  const int blk = blockIdx.x;
  const int b = blk >> 3, slice = blk & 7;
  const int t = threadIdx.x;
  const int idx = slice * 256 + t;        // 0..2047 within this b
  if (t < 2) {
    const int k = slice * 2 + t;
    float a = 0.f;
    for (int tile = 0; tile < TILES; tile++)
      a += g_partAsum[(b * TILES + tile) * K_ + k];
    s_as2[t] = a;
  }
  __syncthreads();
  float e = 0.f;
  const int base = b * TILES * 2048 + idx;
  for (int tile = 0; tile < TILES; tile++) e += g_partE[base + tile * 2048];
  e -= s_as2[t >> 7] * codewords[idx];    // idx == k*128 + d in (K,D) layout
  g_encU[b * 2048 + idx] = e;
  s_red[t] = e * e;
  __syncthreads();
  for (int s = 128; s > 0; s >>= 1) {
    if (t < s) s_red[t] += s_red[t + s];
    __syncthreads();
  }
  if (t == 0) g_sqp[blk] = s_red[0];
}

// ---------------- channel SE (norm folded; also writes normalized enc) ----------------
__global__ __launch_bounds__(256)
void k_chse(const float* __restrict__ se_w, const float* __restrict__ se_b,
            float* __restrict__ out_enc) {
  __shared__ float sw[2048];
  __shared__ float s_rn[16];
  const int c = blockIdx.x;
  const int t = threadIdx.x;
  if (t < 16) {
    float s = 0.f;
#pragma unroll
    for (int j = 0; j < 8; j++) s += g_sqp[t * 8 + j];
    s_rn[t] = 1.f / fmaxf(sqrtf(s), 1e-12f);
  }
  const float* wr = se_w + (size_t)c * 2048;
#pragma unroll
  for (int i = 0; i < 8; i++) sw[t + i * 256] = wr[t + i * 256];
  __syncthreads();
  // write this block's 64-element slice of normalized enc (single batch per block)
  if (t < 64) {
    const int idx = c * 64 + t;            // 512*64 = 32768 = B_*K_*D_
    out_enc[idx] = g_encU[idx] * s_rn[c >> 5];
  }
  const int w = t >> 5, lane = t & 31;
  const float bias = se_b[c];
#pragma unroll
  for (int bb = 0; bb < 2; bb++) {
    const int b = w * 2 + bb;
    const float* er = g_encU + b * 2048;
    float p = 0.f;
#pragma unroll 8
    for (int i = 0; i < 64; i++) {
      const int idx = lane + (i << 5);
      p = fmaf(er[idx], sw[idx], p);
    }
#pragma unroll
    for (int o = 16; o > 0; o >>= 1) p += __shfl_xor_sync(0xffffffffu, p, o);
    if (lane == 0)
      g_chn[b * C_ + c] = 1.f / (1.f + __expf(-fmaf(p, s_rn[b], bias)));
  }
}

// ---------------- final gating: out = x * spa_se * chn_se (streaming hints) ----------------
__global__ void k_out(const float* __restrict__ x, float* __restrict__ out) {
  const int i = blockIdx.x * 256 + threadIdx.x;
  const float4 v = __ldcs(reinterpret_cast<const float4*>(x) + i);
  const int b = i >> 19;
  const int rem = i & 524287;
  const int c = rem >> 10;
  const int n4 = rem & 1023;
  const float4 sp = reinterpret_cast<const float4*>(g_spa)[b * 1024 + n4];
  const float ch = g_chn[b * C_ + c];
  float4 o;
  o.x = v.x * sp.x * ch;
  o.y = v.y * sp.y * ch;
  o.z = v.z * sp.z * ch;
  o.w = v.w * sp.w * ch;
  __stcs(reinterpret_cast<float4*>(out) + i, o);
}

extern "C" void kernel_launch(void* const* d_in, const int* in_sizes, int n_in,
                              void* d_out, int out_size) {
  const float* x    = (const float*)d_in[0];
  const float* pg   = (const float*)d_in[1];
  const float* pb   = (const float*)d_in[2];
  const float* pm   = (const float*)d_in[3];
  const float* pv   = (const float*)d_in[4];
  const float* a1g  = (const float*)d_in[5];
  const float* a1b  = (const float*)d_in[6];
  const float* a1m  = (const float*)d_in[7];
  const float* a1v  = (const float*)d_in[8];
  const float* cwv  = (const float*)d_in[9];   // conv_w (D, C)
  const float* cb   = (const float*)d_in[10];
  const float* a2g  = (const float*)d_in[11];
  const float* a2b  = (const float*)d_in[12];
  const float* a2m  = (const float*)d_in[13];
  const float* a2v  = (const float*)d_in[14];
  const float* cdw  = (const float*)d_in[15];  // codewords (K, D)
  const float* sck  = (const float*)d_in[16];  // scale (K,)
  const float* sew  = (const float*)d_in[17];  // se_w (C, K*D)
  const float* seb  = (const float*)d_in[18];
  const float* spw  = (const float*)d_in[19];  // spa_w (C,)
  float* out = (float*)d_out;

  cudaFuncSetAttribute(k_main, cudaFuncAttributeMaxDynamicSharedMemorySize, SMEM_BYTES);

  k_prep_c<<<2, 256>>>(pg, pb, pm, pv, a1g, a1b, a1m, a1v);
  k_prep_d<<<1, 128>>>(cb, a2g, a2b, a2m, a2v, cdw);
  k_wsplit<<<(D_ * C_ + 255) / 256, 256>>>(cwv);
  k_main<<<GRID_PERSIST, NT, SMEM_BYTES>>>(x, spw, cdw, sck);
  k_red1<<<128, 256>>>(cdw);
  k_chse<<<C_, 256>>>(sew, seb, out);
  k_out<<<(B_ * C_ * NHW / 4) / 256, 256>>>(x, out + B_ * K_ * D_);
}